// round 16
// baseline (speedup 1.0000x reference)
#include <cuda_runtime.h>
#include <cstdint>

#define N_NODES 100000
#define N_EDGES 3200000
#define E4 (N_EDGES / 4)

// Scratch (device globals — zero-initialized at module load; no allocation).
__device__ float  g_deg[N_NODES];    // consume-and-reset each replay
__device__ float  g_dinv[N_NODES];
__device__ float2 g_xs[N_NODES];     // x[i] * dinv[i]
__device__ float2 g_agg1[N_NODES];
__device__ float2 g_ps[N_NODES];     // (h1@W2)[i] * dinv[i]
__device__ float2 g_agg2[N_NODES];

__device__ __forceinline__ void red_add_f2(float2* addr, float2 v) {
    asm volatile("red.global.add.v2.f32 [%0], {%1, %2};"
                 :: "l"(addr), "f"(v.x), "f"(v.y) : "memory");
}
__device__ __forceinline__ void red_add_f(float* addr, float v) {
    asm volatile("red.global.add.f32 [%0], %1;"
                 :: "l"(addr), "f"(v) : "memory");
}

// ---------------------------------------------------------------------------
// PDL pattern: trigger at block top (successor launches into our drain ramp),
// independent input loads BEFORE griddepsync, dependent reads after.

__global__ void k_degree(const int4* __restrict__ dst4) {
    cudaTriggerProgrammaticLaunchCompletion();
    int t = blockIdx.x * blockDim.x + threadIdx.x;
    if (t < E4) {
        int4 d = dst4[t];                         // input: independent
        cudaGridDependencySynchronize();
        red_add_f(&g_deg[d.x], 1.0f);
        red_add_f(&g_deg[d.y], 1.0f);
        red_add_f(&g_deg[d.z], 1.0f);
        red_add_f(&g_deg[d.w], 1.0f);
    }
}

__global__ void k_pre1(const float2* __restrict__ x2) {
    cudaTriggerProgrammaticLaunchCompletion();
    int i = blockIdx.x * blockDim.x + threadIdx.x;
    float2 xi = make_float2(0.f, 0.f);
    if (i < N_NODES) xi = x2[i];                  // input: independent
    cudaGridDependencySynchronize();              // wait for k_degree
    if (i < N_NODES) {
        float dg = g_deg[i];
        g_deg[i] = 0.f;                           // reset for next replay
        float di = rsqrtf(dg + 1.0f);             // +1 self-loop
        g_dinv[i] = di;
        float2 xs = make_float2(xi.x * di, xi.y * di);
        g_xs[i]   = xs;
        g_agg1[i] = xs;                           // self-loop seed
    }
}

__global__ void k_scatter1(const int4* __restrict__ src4,
                           const int4* __restrict__ dst4) {
    cudaTriggerProgrammaticLaunchCompletion();
    int t = blockIdx.x * blockDim.x + threadIdx.x;
    if (t < E4) {
        int4 s = src4[t];                         // inputs: independent
        int4 d = dst4[t];
        cudaGridDependencySynchronize();          // wait for k_pre1
        float2 v0 = __ldg(&g_xs[s.x]);
        float2 v1 = __ldg(&g_xs[s.y]);
        float2 v2 = __ldg(&g_xs[s.z]);
        float2 v3 = __ldg(&g_xs[s.w]);
        red_add_f2(&g_agg1[d.x], v0);
        red_add_f2(&g_agg1[d.y], v1);
        red_add_f2(&g_agg1[d.z], v2);
        red_add_f2(&g_agg1[d.w], v3);
    } else {
        cudaGridDependencySynchronize();
    }
}

// Scalar weight loads, all post-sync (R13 body: 32 regs, measured 6.0us —
// faster than the float4/pre-sync variant which hit 92 regs / 7.4us).
__global__ void k_mid(const float* __restrict__ W1,   // [2,16]
                      const float* __restrict__ b1,   // [16]
                      const float* __restrict__ W2) { // [16,2]
    cudaTriggerProgrammaticLaunchCompletion();
    cudaGridDependencySynchronize();              // wait for k_scatter1
    int i = blockIdx.x * blockDim.x + threadIdx.x;
    if (i >= N_NODES) return;
    float di = g_dinv[i];
    float2 t = g_agg1[i];
    float ax = t.x * di, ay = t.y * di;
    float px = 0.0f, py = 0.0f;
#pragma unroll
    for (int j = 0; j < 16; j++) {
        float h = ax * __ldg(&W1[j]) + ay * __ldg(&W1[16 + j]) + __ldg(&b1[j]);
        h = fmaxf(h, 0.0f);
        px += h * __ldg(&W2[2 * j]);
        py += h * __ldg(&W2[2 * j + 1]);
    }
    float2 ps = make_float2(px * di, py * di);
    g_ps[i]   = ps;
    g_agg2[i] = ps;                               // self-loop seed
}

__global__ void k_scatter2(const int4* __restrict__ src4,
                           const int4* __restrict__ dst4) {
    cudaTriggerProgrammaticLaunchCompletion();
    int t = blockIdx.x * blockDim.x + threadIdx.x;
    if (t < E4) {
        int4 s = src4[t];
        int4 d = dst4[t];
        cudaGridDependencySynchronize();          // wait for k_mid
        float2 v0 = __ldg(&g_ps[s.x]);
        float2 v1 = __ldg(&g_ps[s.y]);
        float2 v2 = __ldg(&g_ps[s.z]);
        float2 v3 = __ldg(&g_ps[s.w]);
        red_add_f2(&g_agg2[d.x], v0);
        red_add_f2(&g_agg2[d.y], v1);
        red_add_f2(&g_agg2[d.z], v2);
        red_add_f2(&g_agg2[d.w], v3);
    } else {
        cudaGridDependencySynchronize();
    }
}

__global__ void k_out(const float* __restrict__ b2, float2* __restrict__ out2) {
    cudaTriggerProgrammaticLaunchCompletion();
    int i = blockIdx.x * blockDim.x + threadIdx.x;
    float bx = __ldg(&b2[0]), by = __ldg(&b2[1]); // inputs: independent
    cudaGridDependencySynchronize();              // wait for k_scatter2
    if (i >= N_NODES) return;
    float di = g_dinv[i];
    float2 t = g_agg2[i];
    float zx = t.x * di + bx;
    float zy = t.y * di + by;
    float m = fmaxf(zx, zy);
    float l = m + __logf(__expf(zx - m) + __expf(zy - m));
    out2[i] = make_float2(zx - l, zy - l);
}

// ---------------------------------------------------------------------------
extern "C" void kernel_launch(void* const* d_in, const int* in_sizes, int n_in,
                              void* d_out, int out_size) {
    const float* x  = (const float*)d_in[0];   // [N,2]
    const int*   ei = (const int*)d_in[1];     // [2,E] int32
    const float* W1 = (const float*)d_in[2];
    const float* b1 = (const float*)d_in[3];
    const float* W2 = (const float*)d_in[4];
    const float* b2 = (const float*)d_in[5];

    const int4* src4 = (const int4*)ei;
    const int4* dst4 = (const int4*)(ei + N_EDGES);
    const float2* x2 = (const float2*)x;
    float2* out2 = (float2*)d_out;

    const int T = 256;
    const int gN  = (N_NODES + T - 1) / T;
    const int gE4 = (E4 + T - 1) / T;

    cudaLaunchAttribute attr;
    attr.id = cudaLaunchAttributeProgrammaticStreamSerialization;
    attr.val.programmaticStreamSerializationAllowed = 1;

    cudaLaunchConfig_t cfg = {};
    cfg.blockDim = dim3(T, 1, 1);
    cfg.dynamicSmemBytes = 0;
    cfg.stream = 0;
    cfg.attrs = &attr;
    cfg.numAttrs = 1;

    // First node: plain launch (no intra-graph predecessor).
    k_degree<<<gE4, T>>>(dst4);

    cfg.gridDim = dim3(gN, 1, 1);
    cudaLaunchKernelEx(&cfg, k_pre1, x2);

    cfg.gridDim = dim3(gE4, 1, 1);
    cudaLaunchKernelEx(&cfg, k_scatter1, src4, dst4);

    cfg.gridDim = dim3(gN, 1, 1);
    cudaLaunchKernelEx(&cfg, k_mid, W1, b1, W2);

    cfg.gridDim = dim3(gE4, 1, 1);
    cudaLaunchKernelEx(&cfg, k_scatter2, src4, dst4);

    cfg.gridDim = dim3(gN, 1, 1);
    cudaLaunchKernelEx(&cfg, k_out, b2, out2);
}